// round 5
// baseline (speedup 1.0000x reference)
#include <cuda_runtime.h>
#include <cuda_bf16.h>

#define BATCH 16
#define LEN   128
#define HID   128
#define G4    512   // 4*HID
#define EMB   128
#define D2    256   // 2*HID

typedef unsigned long long u64;

// ---------------- scratch (device globals; no allocation) ----------------
__device__ float g_x  [BATCH*LEN*EMB];
__device__ float g_xp [2*BATCH*LEN*G4];
__device__ float g_h0 [BATCH*LEN*D2];
__device__ float g_h1 [BATCH*LEN*D2];
__device__ float g_a  [BATCH*LEN*100];
__device__ float g_bp [BATCH*LEN*100];

// ---------------- helpers ----------------
__device__ __forceinline__ float sigf(float x){
    float e = __expf(-x);
    return __fdividef(1.f, 1.f + e);
}
__device__ __forceinline__ float tanhf_(float x){
    float e = __expf(-2.f * x);
    return __fdividef(2.f, 1.f + e) - 1.f;
}
__device__ __forceinline__ void fma2(u64 &d, u64 a, u64 b){
    asm("fma.rn.f32x2 %0, %1, %2, %0;" : "+l"(d) : "l"(a), "l"(b));
}
__device__ __forceinline__ float2 unpack2(u64 v){
    float2 r; asm("mov.b64 {%0,%1}, %2;" : "=f"(r.x), "=f"(r.y) : "l"(v)); return r;
}
__device__ __forceinline__ unsigned smem_u32(const void* p){
    unsigned a;
    asm("{ .reg .u64 t; cvta.to.shared.u64 t, %1; cvt.u32.u64 %0, t; }" : "=r"(a) : "l"(p));
    return a;
}

// ---------------- embedding concat ----------------
__global__ void embed_kernel(const int* __restrict__ widx, const int* __restrict__ pidx,
                             const float* __restrict__ wemb, const float* __restrict__ temb)
{
    int bl = blockIdx.x;
    int d  = threadIdx.x;
    int w = widx[bl];
    int p = pidx[bl];
    float v = (d < 100) ? wemb[w * 100 + d] : temb[p * 28 + (d - 100)];
    g_x[bl * EMB + d] = v;
}

// ---------------- tiled GEMM (R1-proven single-buffer version) ----------------
__global__ __launch_bounds__(256)
void gemm64(const float* __restrict__ A, const float* __restrict__ W,
            const float* __restrict__ b1, const float* __restrict__ b2,
            float* __restrict__ C, int N, int K, int wstride)
{
    __shared__ float As[16][68];
    __shared__ float Ws[16][68];
    int tid = threadIdx.x;
    int tx = tid & 15, ty = tid >> 4;
    int m0 = blockIdx.y * 64, n0 = blockIdx.x * 64;
    int lrow = tid >> 2;
    int lk   = (tid & 3) * 4;
    float acc[4][4];
    #pragma unroll
    for (int i = 0; i < 4; i++)
        #pragma unroll
        for (int j = 0; j < 4; j++) acc[i][j] = 0.f;

    for (int k0 = 0; k0 < K; k0 += 16){
        float4 av = *(const float4*)&A[(size_t)(m0 + lrow) * K + k0 + lk];
        int wn = n0 + lrow;
        float4 wv = make_float4(0.f,0.f,0.f,0.f);
        if (wn < N) wv = *(const float4*)&W[(size_t)wn * wstride + k0 + lk];
        As[lk+0][lrow] = av.x; As[lk+1][lrow] = av.y; As[lk+2][lrow] = av.z; As[lk+3][lrow] = av.w;
        Ws[lk+0][lrow] = wv.x; Ws[lk+1][lrow] = wv.y; Ws[lk+2][lrow] = wv.z; Ws[lk+3][lrow] = wv.w;
        __syncthreads();
        #pragma unroll
        for (int kk = 0; kk < 16; kk++){
            float4 a4 = *(const float4*)&As[kk][ty*4];
            float4 w4 = *(const float4*)&Ws[kk][tx*4];
            float av_[4] = {a4.x, a4.y, a4.z, a4.w};
            float wv_[4] = {w4.x, w4.y, w4.z, w4.w};
            #pragma unroll
            for (int i = 0; i < 4; i++)
                #pragma unroll
                for (int j = 0; j < 4; j++) acc[i][j] = fmaf(av_[i], wv_[j], acc[i][j]);
        }
        __syncthreads();
    }
    #pragma unroll
    for (int j = 0; j < 4; j++){
        int n = n0 + tx*4 + j;
        if (n >= N) continue;
        float bias = (b1 ? b1[n] : 0.f) + (b2 ? b2[n] : 0.f);
        #pragma unroll
        for (int i = 0; i < 4; i++){
            int m = m0 + ty*4 + i;
            C[(size_t)m * N + n] = acc[i][j] + bias;
        }
    }
}

// ---------------- LSTM v5: 4-CTA cluster per (dir,batch) ----------------
// Each CTA owns 32 hidden units (128 gate rows). 512 threads:
//   warp w = tid>>5 (16 warps), lane l = tid&31
//   c = l&1 (unit in pair), g = (l>>1)&3 (gate), q = l>>3 (k-quarter)
//   unit u = rank*32 + w*2 + c ; row r = g*128 + u ; k-range [q*32, q*32+32)
// Per-thread weights: 16 u64 pairs = 32 regs. NO possibility of spill.
// Reduction across quarters via shfl_xor(8), shfl_xor(16).
// h exchange: warp lane0 stores the pair (u, u+1) locally + to 3 peers (DSMEM),
// then release-arrives on each peer's mbar. mbar count = 3 peers * 16 warps = 48.
__global__ __launch_bounds__(512, 1) __cluster_dims__(4, 1, 1)
void lstm_kernel(const float* __restrict__ xp,   // [2][B][L][512]
                 const float* __restrict__ whf,
                 const float* __restrict__ whb,
                 float* __restrict__ hcat)       // [B][L][256]
{
    __shared__ __align__(16) float hf[2][HID];
    __shared__ __align__(8)  u64   mbar[2];

    int tid  = threadIdx.x;
    int w    = tid >> 5;
    int l    = tid & 31;
    int c    = l & 1;
    int g    = (l >> 1) & 3;
    int q    = l >> 3;

    int rank = blockIdx.x & 3;
    int cid  = blockIdx.x >> 2;
    int dir  = cid >> 4;
    int b    = cid & 15;

    int u = rank * 32 + w * 2 + c;
    int r = g * 128 + u;

    const float* wh = dir ? whb : whf;
    const u64* wrow = (const u64*)(wh + (size_t)r * HID) + q * 16;
    u64 wr[16];
    #pragma unroll
    for (int p = 0; p < 16; p++) wr[p] = wrow[p];

    unsigned h_lo[2], mb_lo[2];
    h_lo[0] = smem_u32(&hf[0][0]); h_lo[1] = smem_u32(&hf[1][0]);
    mb_lo[0] = smem_u32(&mbar[0]); mb_lo[1] = smem_u32(&mbar[1]);
    // peer addresses: 3 peers x 2 buffers
    unsigned h_pe[3][2], mb_pe[3][2];
    #pragma unroll
    for (int p = 0; p < 3; p++){
        int pr = (rank + 1 + p) & 3;
        #pragma unroll
        for (int i = 0; i < 2; i++){
            asm("mapa.shared::cluster.u32 %0, %1, %2;" : "=r"(h_pe[p][i])  : "r"(h_lo[i]),  "r"(pr));
            asm("mapa.shared::cluster.u32 %0, %1, %2;" : "=r"(mb_pe[p][i]) : "r"(mb_lo[i]), "r"(pr));
        }
    }

    if (tid < 256) ((float*)hf)[tid] = 0.f;
    if (tid == 0){
        asm volatile("mbarrier.init.shared.b64 [%0], 48;" :: "r"(mb_lo[0]) : "memory");
        asm volatile("mbarrier.init.shared.b64 [%0], 48;" :: "r"(mb_lo[1]) : "memory");
    }
    __syncthreads();
    asm volatile("barrier.cluster.arrive.aligned;" ::: "memory");
    asm volatile("barrier.cluster.wait.aligned;"   ::: "memory");

    float cst = 0.f;
    int ph0 = 0, ph1 = 0;

    const float* xpd = xp + ((size_t)(dir * BATCH + b)) * LEN * G4 + r;
    bool  is_t = (g == 2);
    float act_m = is_t ? 2.f : 1.f;
    float act_b = is_t ? -1.f : 0.f;
    float pre_m = is_t ? 2.f : 1.f;

    int t  = dir ? (LEN - 1) : 0;
    int dt = dir ? -1 : 1;
    unsigned wr_off = (unsigned)(rank * 32 + w * 2) * 4u;

    float xg = xpd[t * G4];

    for (int s = 0; s < LEN; s++){
        float xg_next = (s < LEN - 1) ? xpd[(t + dt) * G4] : 0.f;

        const ulonglong2* hb = (const ulonglong2*)(&hf[s & 1][q * 32]);
        u64 a0 = 0ull, a1 = 0ull;
        #pragma unroll
        for (int i = 0; i < 8; i++){
            ulonglong2 hv2 = hb[i];
            fma2(a0, wr[2*i],   hv2.x);
            fma2(a1, wr[2*i+1], hv2.y);
        }
        float2 p0 = unpack2(a0);
        float2 p1 = unpack2(a1);
        float red = (p0.x + p0.y) + (p1.x + p1.y);
        red += __shfl_xor_sync(0xffffffffu, red, 8);
        red += __shfl_xor_sync(0xffffffffu, red, 16);
        float pre = red + xg;

        float sv  = sigf(pre * pre_m);
        float val = fmaf(act_m, sv, act_b);

        // gates of unit c live at lanes c+2g (q=0 copies identical everywhere)
        float vi = __shfl_sync(0xffffffffu, val, c);
        float vf = __shfl_sync(0xffffffffu, val, c + 2);
        float vg = __shfl_sync(0xffffffffu, val, c + 4);
        float vo = __shfl_sync(0xffffffffu, val, c + 6);

        cst = vf * cst + vi * vg;
        float hv = vo * tanhf_(cst);

        float hv1 = __shfl_sync(0xffffffffu, hv, 1);   // unit u_base+1 (from lane 1)
        int nb = (s & 1) ^ 1;
        if (l == 0){
            // hv = unit u_base, hv1 = unit u_base+1
            *(float2*)&hcat[((size_t)b * LEN + t) * D2 + dir * HID + rank * 32 + w * 2] =
                make_float2(hv, hv1);
            if (s < LEN - 1){
                *(float2*)&hf[nb][rank * 32 + w * 2] = make_float2(hv, hv1);
                #pragma unroll
                for (int p = 0; p < 3; p++){
                    asm volatile("st.shared::cluster.v2.f32 [%0], {%1,%2};"
                                 :: "r"(h_pe[p][nb] + wr_off), "f"(hv), "f"(hv1) : "memory");
                }
                #pragma unroll
                for (int p = 0; p < 3; p++){
                    asm volatile("mbarrier.arrive.release.cluster.shared::cluster.b64 _, [%0];"
                                 :: "r"(mb_pe[p][nb]) : "memory");
                }
            }
        }
        __syncthreads();
        if (s < LEN - 1){
            unsigned mba = mb_lo[nb];
            unsigned par = (unsigned)(nb ? ph1 : ph0);
            unsigned done;
            asm volatile(
                "{\n\t.reg .pred p;\n\t"
                "mbarrier.try_wait.parity.acquire.cluster.shared::cta.b64 p, [%1], %2;\n\t"
                "selp.b32 %0, 1, 0, p;\n\t}"
                : "=r"(done) : "r"(mba), "r"(par) : "memory");
            if (!done){
                asm volatile(
                    "{\n\t.reg .pred P1;\n\t"
                    "WL_%=:\n\t"
                    "mbarrier.try_wait.parity.acquire.cluster.shared::cta.b64 P1, [%0], %1, 0x989680;\n\t"
                    "@P1 bra.uni WD_%=;\n\t"
                    "bra.uni WL_%=;\n\t"
                    "WD_%=:\n\t}"
                    :: "r"(mba), "r"(par) : "memory");
            }
            if (nb) ph1 ^= 1; else ph0 ^= 1;
        }
        t += dt;
        xg = xg_next;
    }

    asm volatile("barrier.cluster.arrive.aligned;" ::: "memory");
    asm volatile("barrier.cluster.wait.aligned;"   ::: "memory");
}

// ---------------- biaffine scorer ----------------
__global__ __launch_bounds__(128)
void scores_kernel(const float* __restrict__ w2, const float* __restrict__ b2,
                   float* __restrict__ out)
{
    int i  = blockIdx.x;
    int bq = blockIdx.y;
    int j  = threadIdx.x;
    __shared__ float a_sh[4][100];
    __shared__ float w2_sh[100];
    if (j < 100){
        w2_sh[j] = w2[j];
        #pragma unroll
        for (int bi = 0; bi < 4; bi++)
            a_sh[bi][j] = g_a[((size_t)(bq*4+bi) * LEN + i) * 100 + j];
    }
    __syncthreads();
    float bb = b2[0];
    for (int bi = 0; bi < 4; bi++){
        int b = bq * 4 + bi;
        const float* bpr = g_bp + ((size_t)b * LEN + j) * 100;
        float acc = bb;
        #pragma unroll 4
        for (int k = 0; k < 100; k++)
            acc = fmaf(tanhf_(a_sh[bi][k] + bpr[k]), w2_sh[k], acc);
        out[(size_t)(i * LEN + j) * BATCH + b] = acc;
    }
}

// ---------------- launch ----------------
extern "C" void kernel_launch(void* const* d_in, const int* in_sizes, int n_in,
                              void* d_out, int out_size)
{
    const int*   widx = (const int*)  d_in[0];
    const int*   pidx = (const int*)  d_in[1];
    const float* wemb = (const float*)d_in[4];
    const float* temb = (const float*)d_in[5];
    const float* w_ih_l0f = (const float*)d_in[6];
    const float* w_hh_l0f = (const float*)d_in[7];
    const float* b_ih_l0f = (const float*)d_in[8];
    const float* b_hh_l0f = (const float*)d_in[9];
    const float* w_ih_l0b = (const float*)d_in[10];
    const float* w_hh_l0b = (const float*)d_in[11];
    const float* b_ih_l0b = (const float*)d_in[12];
    const float* b_hh_l0b = (const float*)d_in[13];
    const float* w_ih_l1f = (const float*)d_in[14];
    const float* w_hh_l1f = (const float*)d_in[15];
    const float* b_ih_l1f = (const float*)d_in[16];
    const float* b_hh_l1f = (const float*)d_in[17];
    const float* w_ih_l1b = (const float*)d_in[18];
    const float* w_hh_l1b = (const float*)d_in[19];
    const float* b_ih_l1b = (const float*)d_in[20];
    const float* b_hh_l1b = (const float*)d_in[21];
    const float* fc1_w = (const float*)d_in[22];
    const float* fc1_b = (const float*)d_in[23];
    const float* fc2_w = (const float*)d_in[24];
    const float* fc2_b = (const float*)d_in[25];
    float* out = (float*)d_out;

    float *p_x, *p_xp, *p_h0, *p_h1, *p_a, *p_bp;
    cudaGetSymbolAddress((void**)&p_x,   g_x);
    cudaGetSymbolAddress((void**)&p_xp,  g_xp);
    cudaGetSymbolAddress((void**)&p_h0,  g_h0);
    cudaGetSymbolAddress((void**)&p_h1,  g_h1);
    cudaGetSymbolAddress((void**)&p_a,   g_a);
    cudaGetSymbolAddress((void**)&p_bp,  g_bp);

    const int M = BATCH * LEN;   // 2048

    embed_kernel<<<M, 128>>>(widx, pidx, wemb, temb);

    gemm64<<<dim3(8, 32), 256>>>(p_x, w_ih_l0f, b_ih_l0f, b_hh_l0f, p_xp,            G4, EMB, EMB);
    gemm64<<<dim3(8, 32), 256>>>(p_x, w_ih_l0b, b_ih_l0b, b_hh_l0b, p_xp + (size_t)M*G4, G4, EMB, EMB);
    lstm_kernel<<<128, 512>>>(p_xp, w_hh_l0f, w_hh_l0b, p_h0);

    gemm64<<<dim3(8, 32), 256>>>(p_h0, w_ih_l1f, b_ih_l1f, b_hh_l1f, p_xp,           G4, D2, D2);
    gemm64<<<dim3(8, 32), 256>>>(p_h0, w_ih_l1b, b_ih_l1b, b_hh_l1b, p_xp + (size_t)M*G4, G4, D2, D2);
    lstm_kernel<<<128, 512>>>(p_xp, w_hh_l1f, w_hh_l1b, p_h1);

    gemm64<<<dim3(2, 32), 256>>>(p_h1, fc1_w,      nullptr, nullptr, p_a,  100, D2, 512);
    gemm64<<<dim3(2, 32), 256>>>(p_h1, fc1_w + D2, fc1_b,   nullptr, p_bp, 100, D2, 512);

    scores_kernel<<<dim3(128, 4), 128>>>(fc2_w, fc2_b, out);
    (void)in_sizes; (void)n_in; (void)out_size;
}

// round 6
// speedup vs baseline: 1.7855x; 1.7855x over previous
#include <cuda_runtime.h>
#include <cuda_bf16.h>

#define BATCH 16
#define LEN   128
#define HID   128
#define G4    512   // 4*HID
#define EMB   128
#define D2    256   // 2*HID

typedef unsigned long long u64;

// ---------------- scratch (device globals; no allocation) ----------------
__device__ float g_x  [BATCH*LEN*EMB];
__device__ float g_xp [2*BATCH*LEN*G4];
__device__ float g_h0 [BATCH*LEN*D2];
__device__ float g_h1 [BATCH*LEN*D2];
__device__ float g_a  [BATCH*LEN*100];
__device__ float g_bp [BATCH*LEN*100];

// ---------------- helpers ----------------
__device__ __forceinline__ float sigf(float x){
    float e = __expf(-x);
    return __fdividef(1.f, 1.f + e);
}
__device__ __forceinline__ float tanhf_(float x){
    float e = __expf(-2.f * x);
    return __fdividef(2.f, 1.f + e) - 1.f;
}
__device__ __forceinline__ void fma2(u64 &d, u64 a, u64 b){
    asm("fma.rn.f32x2 %0, %1, %2, %0;" : "+l"(d) : "l"(a), "l"(b));
}
__device__ __forceinline__ float2 unpack2(u64 v){
    float2 r; asm("mov.b64 {%0,%1}, %2;" : "=f"(r.x), "=f"(r.y) : "l"(v)); return r;
}
__device__ __forceinline__ unsigned smem_u32(const void* p){
    unsigned a;
    asm("{ .reg .u64 t; cvta.to.shared.u64 t, %1; cvt.u32.u64 %0, t; }" : "=r"(a) : "l"(p));
    return a;
}

// ---------------- embedding concat ----------------
__global__ void embed_kernel(const int* __restrict__ widx, const int* __restrict__ pidx,
                             const float* __restrict__ wemb, const float* __restrict__ temb)
{
    int bl = blockIdx.x;
    int d  = threadIdx.x;
    int w = widx[bl];
    int p = pidx[bl];
    float v = (d < 100) ? wemb[w * 100 + d] : temb[p * 28 + (d - 100)];
    g_x[bl * EMB + d] = v;
}

// ---------------- tiled GEMM, R1 body, f/b merged on blockIdx.z ----------------
__global__ __launch_bounds__(256)
void gemm64(const float* __restrict__ A,
            const float* __restrict__ W0, const float* __restrict__ W1,
            const float* __restrict__ b1_0, const float* __restrict__ b1_1,
            const float* __restrict__ b2_0, const float* __restrict__ b2_1,
            float* __restrict__ C0, float* __restrict__ C1,
            int N, int K, int wstride)
{
    __shared__ float As[16][68];
    __shared__ float Ws[16][68];
    int z = blockIdx.z;
    const float* W  = z ? W1   : W0;
    const float* b1 = z ? b1_1 : b1_0;
    const float* b2 = z ? b2_1 : b2_0;
    float* C        = z ? C1   : C0;

    int tid = threadIdx.x;
    int tx = tid & 15, ty = tid >> 4;
    int m0 = blockIdx.y * 64, n0 = blockIdx.x * 64;
    int lrow = tid >> 2;
    int lk   = (tid & 3) * 4;
    float acc[4][4];
    #pragma unroll
    for (int i = 0; i < 4; i++)
        #pragma unroll
        for (int j = 0; j < 4; j++) acc[i][j] = 0.f;

    for (int k0 = 0; k0 < K; k0 += 16){
        float4 av = *(const float4*)&A[(size_t)(m0 + lrow) * K + k0 + lk];
        int wn = n0 + lrow;
        float4 wv = make_float4(0.f,0.f,0.f,0.f);
        if (wn < N) wv = *(const float4*)&W[(size_t)wn * wstride + k0 + lk];
        As[lk+0][lrow] = av.x; As[lk+1][lrow] = av.y; As[lk+2][lrow] = av.z; As[lk+3][lrow] = av.w;
        Ws[lk+0][lrow] = wv.x; Ws[lk+1][lrow] = wv.y; Ws[lk+2][lrow] = wv.z; Ws[lk+3][lrow] = wv.w;
        __syncthreads();
        #pragma unroll
        for (int kk = 0; kk < 16; kk++){
            float4 a4 = *(const float4*)&As[kk][ty*4];
            float4 w4 = *(const float4*)&Ws[kk][tx*4];
            float av_[4] = {a4.x, a4.y, a4.z, a4.w};
            float wv_[4] = {w4.x, w4.y, w4.z, w4.w};
            #pragma unroll
            for (int i = 0; i < 4; i++)
                #pragma unroll
                for (int j = 0; j < 4; j++) acc[i][j] = fmaf(av_[i], wv_[j], acc[i][j]);
        }
        __syncthreads();
    }
    #pragma unroll
    for (int j = 0; j < 4; j++){
        int n = n0 + tx*4 + j;
        if (n >= N) continue;
        float bias = (b1 ? b1[n] : 0.f) + (b2 ? b2[n] : 0.f);
        #pragma unroll
        for (int i = 0; i < 4; i++){
            int m = m0 + ty*4 + i;
            C[(size_t)m * N + n] = acc[i][j] + bias;
        }
    }
}

// ---------------- LSTM (R3 structure, best measured) + xg prefetch ----------------
// 2-CTA cluster per (dir,batch). Rank owns 64 hidden units (256 gate rows).
// 512 threads: warp=tid>>5, l=tid&31, c=l&3, g=(l>>2)&3, half=l>>4.
// unit u = rank*64 + warp*4 + c ; row r = g*128 + u; thread holds 64 k (half) in 32 u64 regs.
__global__ __launch_bounds__(512, 1) __cluster_dims__(2, 1, 1)
void lstm_kernel(const float* __restrict__ xp,   // [2][B][L][512]
                 const float* __restrict__ whf,
                 const float* __restrict__ whb,
                 float* __restrict__ hcat)       // [B][L][256]
{
    __shared__ __align__(16) float hf[2][HID];
    __shared__ __align__(8)  u64   mbar[2];

    int tid  = threadIdx.x;
    int warp = tid >> 5;
    int l    = tid & 31;
    int c    = l & 3;
    int g    = (l >> 2) & 3;
    int half = l >> 4;

    int rank = blockIdx.x & 1;
    int cid  = blockIdx.x >> 1;
    int dir  = cid >> 4;
    int b    = cid & 15;

    int u  = rank * 64 + warp * 4 + c;
    int r  = g * 128 + u;

    const float* wh = dir ? whb : whf;
    const u64* wrow = (const u64*)(wh + (size_t)r * HID) + half * 32;
    u64 wr[32];
    #pragma unroll
    for (int p = 0; p < 32; p++) wr[p] = wrow[p];

    unsigned h_lo[2], mb_lo[2], h_pe[2], mb_pe[2];
    h_lo[0] = smem_u32(&hf[0][0]); h_lo[1] = smem_u32(&hf[1][0]);
    mb_lo[0] = smem_u32(&mbar[0]); mb_lo[1] = smem_u32(&mbar[1]);
    int peer = rank ^ 1;
    #pragma unroll
    for (int i = 0; i < 2; i++){
        asm("mapa.shared::cluster.u32 %0, %1, %2;" : "=r"(h_pe[i])  : "r"(h_lo[i]),  "r"(peer));
        asm("mapa.shared::cluster.u32 %0, %1, %2;" : "=r"(mb_pe[i]) : "r"(mb_lo[i]), "r"(peer));
    }

    if (tid < 256) ((float*)hf)[tid] = 0.f;
    if (tid == 0){
        asm volatile("mbarrier.init.shared.b64 [%0], 16;" :: "r"(mb_lo[0]) : "memory");
        asm volatile("mbarrier.init.shared.b64 [%0], 16;" :: "r"(mb_lo[1]) : "memory");
    }
    __syncthreads();
    asm volatile("barrier.cluster.arrive.aligned;" ::: "memory");
    asm volatile("barrier.cluster.wait.aligned;"   ::: "memory");

    float cst = 0.f;
    int ph[2] = {0, 0};

    const float* xpd = xp + ((size_t)(dir * BATCH + b)) * LEN * G4 + r;
    bool  is_t = (g == 2);
    float act_m = is_t ? 2.f : 1.f;
    float act_b = is_t ? -1.f : 0.f;
    float pre_m = is_t ? 2.f : 1.f;

    int t  = dir ? (LEN - 1) : 0;
    int dt = dir ? -1 : 1;
    unsigned wr_off = (unsigned)(rank * 64 + warp * 4) * 4u;

    float xg = xpd[t * G4];                       // prefetch step 0

    for (int s = 0; s < LEN; s++){
        float xg_next = (s < LEN - 1) ? xpd[(t + dt) * G4] : 0.f;   // hidden across barrier

        const ulonglong2* hb = (const ulonglong2*)(&hf[s & 1][half * 64]);
        u64 a0 = 0ull, a1 = 0ull;
        #pragma unroll
        for (int i = 0; i < 16; i++){
            ulonglong2 hv = hb[i];
            fma2(a0, wr[2*i],   hv.x);
            fma2(a1, wr[2*i+1], hv.y);
        }
        float2 p0 = unpack2(a0);
        float2 p1 = unpack2(a1);
        float ph_sum = (p0.x + p0.y) + (p1.x + p1.y);
        if (half == 0) ph_sum += xg;
        float pre = ph_sum + __shfl_xor_sync(0xffffffffu, ph_sum, 16);

        float sv  = sigf(pre * pre_m);
        float val = fmaf(act_m, sv, act_b);

        float vi = __shfl_sync(0xffffffffu, val, c);
        float vf = __shfl_sync(0xffffffffu, val, 4 + c);
        float vg = __shfl_sync(0xffffffffu, val, 8 + c);
        float vo = __shfl_sync(0xffffffffu, val, 12 + c);

        cst = vf * cst + vi * vg;
        float hv = vo * tanhf_(cst);

        float h1v = __shfl_sync(0xffffffffu, hv, 1);
        float h2v = __shfl_sync(0xffffffffu, hv, 2);
        float h3v = __shfl_sync(0xffffffffu, hv, 3);
        int nb = (s & 1) ^ 1;
        if (l == 0){
            *(float4*)&hcat[((size_t)b * LEN + t) * D2 + dir * HID + rank * 64 + warp * 4] =
                make_float4(hv, h1v, h2v, h3v);
            if (s < LEN - 1){
                *(float4*)&hf[nb][rank * 64 + warp * 4] = make_float4(hv, h1v, h2v, h3v);
                asm volatile("st.shared::cluster.v4.f32 [%0], {%1,%2,%3,%4};"
                             :: "r"(h_pe[nb] + wr_off), "f"(hv), "f"(h1v), "f"(h2v), "f"(h3v)
                             : "memory");
                asm volatile("mbarrier.arrive.release.cluster.shared::cluster.b64 _, [%0];"
                             :: "r"(mb_pe[nb]) : "memory");
            }
        }
        if (s < LEN - 1){
            __syncthreads();
            unsigned mba = mb_lo[nb];
            unsigned par = (unsigned)ph[nb];
            unsigned done;
            asm volatile(
                "{\n\t.reg .pred p;\n\t"
                "mbarrier.try_wait.parity.acquire.cluster.shared::cta.b64 p, [%1], %2;\n\t"
                "selp.b32 %0, 1, 0, p;\n\t}"
                : "=r"(done) : "r"(mba), "r"(par) : "memory");
            if (!done){
                asm volatile(
                    "{\n\t.reg .pred P1;\n\t"
                    "WL_%=:\n\t"
                    "mbarrier.try_wait.parity.acquire.cluster.shared::cta.b64 P1, [%0], %1, 0x989680;\n\t"
                    "@P1 bra.uni WD_%=;\n\t"
                    "bra.uni WL_%=;\n\t"
                    "WD_%=:\n\t}"
                    :: "r"(mba), "r"(par) : "memory");
            }
            ph[nb] ^= 1;
        }
        t += dt;
        xg = xg_next;
    }

    asm volatile("barrier.cluster.arrive.aligned;" ::: "memory");
    asm volatile("barrier.cluster.wait.aligned;"   ::: "memory");
}

// ---------------- biaffine scorer ----------------
__global__ __launch_bounds__(128)
void scores_kernel(const float* __restrict__ w2, const float* __restrict__ b2,
                   float* __restrict__ out)
{
    int i  = blockIdx.x;
    int bq = blockIdx.y;
    int j  = threadIdx.x;
    __shared__ float a_sh[4][100];
    __shared__ float w2_sh[100];
    if (j < 100){
        w2_sh[j] = w2[j];
        #pragma unroll
        for (int bi = 0; bi < 4; bi++)
            a_sh[bi][j] = g_a[((size_t)(bq*4+bi) * LEN + i) * 100 + j];
    }
    __syncthreads();
    float bb = b2[0];
    for (int bi = 0; bi < 4; bi++){
        int b = bq * 4 + bi;
        const float* bpr = g_bp + ((size_t)b * LEN + j) * 100;
        float acc = bb;
        #pragma unroll 4
        for (int k = 0; k < 100; k++)
            acc = fmaf(tanhf_(a_sh[bi][k] + bpr[k]), w2_sh[k], acc);
        out[(size_t)(i * LEN + j) * BATCH + b] = acc;
    }
}

// ---------------- launch ----------------
extern "C" void kernel_launch(void* const* d_in, const int* in_sizes, int n_in,
                              void* d_out, int out_size)
{
    const int*   widx = (const int*)  d_in[0];
    const int*   pidx = (const int*)  d_in[1];
    const float* wemb = (const float*)d_in[4];
    const float* temb = (const float*)d_in[5];
    const float* w_ih_l0f = (const float*)d_in[6];
    const float* w_hh_l0f = (const float*)d_in[7];
    const float* b_ih_l0f = (const float*)d_in[8];
    const float* b_hh_l0f = (const float*)d_in[9];
    const float* w_ih_l0b = (const float*)d_in[10];
    const float* w_hh_l0b = (const float*)d_in[11];
    const float* b_ih_l0b = (const float*)d_in[12];
    const float* b_hh_l0b = (const float*)d_in[13];
    const float* w_ih_l1f = (const float*)d_in[14];
    const float* w_hh_l1f = (const float*)d_in[15];
    const float* b_ih_l1f = (const float*)d_in[16];
    const float* b_hh_l1f = (const float*)d_in[17];
    const float* w_ih_l1b = (const float*)d_in[18];
    const float* w_hh_l1b = (const float*)d_in[19];
    const float* b_ih_l1b = (const float*)d_in[20];
    const float* b_hh_l1b = (const float*)d_in[21];
    const float* fc1_w = (const float*)d_in[22];
    const float* fc1_b = (const float*)d_in[23];
    const float* fc2_w = (const float*)d_in[24];
    const float* fc2_b = (const float*)d_in[25];
    float* out = (float*)d_out;

    float *p_x, *p_xp, *p_h0, *p_h1, *p_a, *p_bp;
    cudaGetSymbolAddress((void**)&p_x,   g_x);
    cudaGetSymbolAddress((void**)&p_xp,  g_xp);
    cudaGetSymbolAddress((void**)&p_h0,  g_h0);
    cudaGetSymbolAddress((void**)&p_h1,  g_h1);
    cudaGetSymbolAddress((void**)&p_a,   g_a);
    cudaGetSymbolAddress((void**)&p_bp,  g_bp);

    const int M = BATCH * LEN;   // 2048

    embed_kernel<<<M, 128>>>(widx, pidx, wemb, temb);

    // layer 0 input projections, f+b in one launch
    gemm64<<<dim3(8, 32, 2), 256>>>(p_x,
        w_ih_l0f, w_ih_l0b, b_ih_l0f, b_ih_l0b, b_hh_l0f, b_hh_l0b,
        p_xp, p_xp + (size_t)M*G4, G4, EMB, EMB);
    lstm_kernel<<<64, 512>>>(p_xp, w_hh_l0f, w_hh_l0b, p_h0);

    // layer 1
    gemm64<<<dim3(8, 32, 2), 256>>>(p_h0,
        w_ih_l1f, w_ih_l1b, b_ih_l1f, b_ih_l1b, b_hh_l1f, b_hh_l1b,
        p_xp, p_xp + (size_t)M*G4, G4, D2, D2);
    lstm_kernel<<<64, 512>>>(p_xp, w_hh_l1f, w_hh_l1b, p_h1);

    // fc1 split projections in one launch: a = h@wa^T ; bp = h@wb^T + fc1_b
    gemm64<<<dim3(2, 32, 2), 256>>>(p_h1,
        fc1_w, fc1_w + D2, (const float*)nullptr, fc1_b,
        (const float*)nullptr, (const float*)nullptr,
        p_a, p_bp, 100, D2, 512);

    // scores
    scores_kernel<<<dim3(128, 4), 128>>>(fc2_w, fc2_b, out);
    (void)in_sizes; (void)n_in; (void)out_size;
}